// round 5
// baseline (speedup 1.0000x reference)
#include <cuda_runtime.h>
#include <math.h>

#define NIMG  4
#define KTOT  4507
#define PITCH 4608
typedef unsigned long long ull;

__constant__ int c_HW[5]   = {40000, 10000, 2500, 625, 169};
__constant__ int c_AOFF[5] = {0, 120000, 150000, 157500, 159375};
__constant__ int c_KL[5]   = {1000, 1000, 1000, 1000, 507};

// ------------- scratch (static device globals; zero-init, no allocs) -------------
__device__ int           g_pos_anchor[NIMG * PITCH];
__device__ float         g_pos_logit [NIMG * PITCH];
__device__ int           g_srt_pos   [NIMG * PITCH];
__device__ float         g_score_srt [NIMG * PITCH];
__device__ float4        g_box       [NIMG * PITCH];
__device__ unsigned char g_lvlvalid  [NIMG * PITCH];
__device__ unsigned char g_keepj     [NIMG * PITCH];
__device__ int           g_list      [NIMG * 5 * 1024];
__device__ float4        g_lbox      [NIMG * 5 * 1024];
__device__ unsigned char g_lvalid    [NIMG * 5 * 1024];
__device__ ull           g_bits      [NIMG * 5 * 1024 * 16];

// ------------- helpers -------------
__device__ __forceinline__ unsigned ordf(float f) {
    unsigned u = __float_as_uint(f);
    return u ^ ((u & 0x80000000u) ? 0xFFFFFFFFu : 0x80000000u);
}
__device__ __forceinline__ float ordinv(unsigned u) {
    unsigned m = (u & 0x80000000u) ? 0x80000000u : 0xFFFFFFFFu;
    return __uint_as_float(u ^ m);
}

template <int NT, bool DESC, typename T>
__device__ void bitonic_sort(T* s, int tid, int nthr) {
    for (int k = 2; k <= NT; k <<= 1) {
        for (int j = k >> 1; j > 0; j >>= 1) {
            __syncthreads();
            for (int i = tid; i < NT; i += nthr) {
                int ixj = i ^ j;
                if (ixj > i) {
                    T a = s[i], b = s[ixj];
                    bool up = ((i & k) == 0);
                    if (DESC) up = !up;
                    bool sw = up ? (a > b) : (a < b);
                    if (sw) { s[i] = b; s[ixj] = a; }
                }
            }
        }
    }
    __syncthreads();
}

// modern XLA logistic expansion: 1 / (1 + exp(-x)), exp = libdevice expf
__device__ __forceinline__ float xla_sigmoid(float x) {
    float e = expf(-x);
    return __fdiv_rn(1.0f, __fadd_rn(1.0f, e));
}

// ------------- K1: per-(level,image) radix-select top-k + rank sort -------------
__global__ __launch_bounds__(512) void k1_topk(
    const float* __restrict__ o0, const float* __restrict__ o1,
    const float* __restrict__ o2, const float* __restrict__ o3,
    const float* __restrict__ o4)
{
    __shared__ unsigned hist[256];
    __shared__ ull      skey[1024];
    __shared__ unsigned eqbuf[1024];
    __shared__ int s_cntG, s_cntE;
    __shared__ unsigned s_prefix;
    __shared__ int s_need;

    const int lvl = blockIdx.x, n = blockIdx.y, tid = threadIdx.x;
    const float* objs[5] = {o0, o1, o2, o3, o4};
    const int HW = c_HW[lvl], k = c_KL[lvl], aoff = c_AOFF[lvl];
    const float* base = objs[lvl] + (size_t)n * 3 * HW;

    unsigned prefix = 0; int need = k;
    for (int shift = 24; shift >= 0; shift -= 8) {
        for (int t = tid; t < 256; t += 512) hist[t] = 0;
        __syncthreads();
        unsigned hm = (shift == 24) ? 0u : (0xFFFFFFFFu << (shift + 8));
        for (int a = 0; a < 3; a++) {
            const float* pl = base + a * HW;
            for (int hw = tid; hw < HW; hw += 512) {
                unsigned u = ordf(pl[hw]);
                if ((u & hm) == prefix) atomicAdd(&hist[(u >> shift) & 255], 1u);
            }
        }
        __syncthreads();
        if (tid == 0) {
            int cum = 0, b = 255;
            for (; b > 0; b--) { int c = (int)hist[b]; if (cum + c >= need) break; cum += c; }
            s_prefix = prefix | ((unsigned)b << shift);
            s_need = need - cum;
        }
        __syncthreads();
        prefix = s_prefix; need = s_need;
        __syncthreads();
    }
    const unsigned T = prefix;
    const int k_eq = need;

    if (tid == 0) { s_cntG = 0; s_cntE = 0; }
    __syncthreads();
    for (int a = 0; a < 3; a++) {
        const float* pl = base + a * HW;
        for (int hw = tid; hw < HW; hw += 512) {
            unsigned u = ordf(pl[hw]);
            int p = hw * 3 + a;
            if (u > T) {
                int s = atomicAdd(&s_cntG, 1);
                skey[s] = ((ull)u << 32) | (unsigned)~(unsigned)(aoff + p);
            } else if (u == T) {
                int e = atomicAdd(&s_cntE, 1);
                if (e < 1024) eqbuf[e] = (unsigned)(aoff + p);
            }
        }
    }
    __syncthreads();
    const int cntG = s_cntG, cntE = s_cntE;
    for (int t = tid; t < 1024; t += 512) if (t >= cntE) eqbuf[t] = 0xFFFFFFFFu;
    bitonic_sort<1024, false, unsigned>(eqbuf, tid, 512);   // index ascending
    for (int t = tid; t < k_eq; t += 512)
        skey[cntG + t] = ((ull)T << 32) | (unsigned)~eqbuf[t];
    for (int t = tid; t < 1024; t += 512) if (t >= k) skey[t] = 0ULL;
    bitonic_sort<1024, true, ull>(skey, tid, 512);          // (logit desc, idx asc)
    for (int r = tid; r < k; r += 512) {
        ull kk = skey[r];
        unsigned idx = ~(unsigned)(kk & 0xFFFFFFFFull);
        g_pos_anchor[n * PITCH + lvl * 1000 + r] = (int)idx;
        g_pos_logit [n * PITCH + lvl * 1000 + r] = ordinv((unsigned)(kk >> 32));
    }
}

// ------------- K2: per-image global sort by (sigmoid desc, pos asc) -------------
__global__ __launch_bounds__(1024) void k2_sort()
{
    extern __shared__ ull sk[];
    const int n = blockIdx.x, tid = threadIdx.x;
    for (int t = tid; t < 8192; t += 1024) {
        ull key = 0ULL;
        if (t < KTOT) {
            float s = xla_sigmoid(g_pos_logit[n * PITCH + t]);
            key = ((ull)ordf(s) << 32) | (unsigned)(65535 - t);
        }
        sk[t] = key;
    }
    bitonic_sort<8192, true, ull>(sk, tid, 1024);
    for (int t = tid; t < KTOT; t += 1024) {
        ull key = sk[t];
        int pos = 65535 - (int)(key & 0xFFFFull);
        g_srt_pos  [n * PITCH + t] = pos;
        g_score_srt[n * PITCH + t] = ordinv((unsigned)(key >> 32));
    }
}

// ------------- K3: decode + clip + validity for sorted entries -------------
__global__ __launch_bounds__(256) void k3_decode(
    const float* __restrict__ d0, const float* __restrict__ d1,
    const float* __restrict__ d2, const float* __restrict__ d3,
    const float* __restrict__ d4, const float* __restrict__ anch)
{
    const int n = blockIdx.y;
    const int j = blockIdx.x * blockDim.x + threadIdx.x;
    if (j >= KTOT) return;
    int pos = g_srt_pos[n * PITCH + j];
    int idx = g_pos_anchor[n * PITCH + pos];
    int lvl = pos / 1000;
    const float* dls[5] = {d0, d1, d2, d3, d4};
    int HW = c_HW[lvl];
    int p = idx - c_AOFF[lvl];
    int a = p % 3, hw = p / 3;
    const float* dl = dls[lvl] + (size_t)n * 12 * HW + (size_t)(a * 4) * HW + hw;
    float dx = dl[0], dy = dl[HW], dwv = dl[2 * HW], dhv = dl[3 * HW];
    float4 an = ((const float4*)anch)[idx];
    float wa  = __fsub_rn(an.z, an.x), ha = __fsub_rn(an.w, an.y);
    float cxa = __fadd_rn(an.x, __fmul_rn(0.5f, wa));
    float cya = __fadd_rn(an.y, __fmul_rn(0.5f, ha));
    const float CL = 4.135166556742356f;
    dwv = fminf(dwv, CL); dhv = fminf(dhv, CL);
    float cx = __fadd_rn(__fmul_rn(dx, wa), cxa);
    float cy = __fadd_rn(__fmul_rn(dy, ha), cya);
    float w = __fmul_rn(expf(dwv), wa);
    float h = __fmul_rn(expf(dhv), ha);
    float x1 = __fsub_rn(cx, __fmul_rn(0.5f, w));
    float y1 = __fsub_rn(cy, __fmul_rn(0.5f, h));
    float x2 = __fadd_rn(cx, __fmul_rn(0.5f, w));
    float y2 = __fadd_rn(cy, __fmul_rn(0.5f, h));
    x1 = fminf(fmaxf(x1, 0.f), 800.f);  y1 = fminf(fmaxf(y1, 0.f), 800.f);
    x2 = fminf(fmaxf(x2, 0.f), 800.f);  y2 = fminf(fmaxf(y2, 0.f), 800.f);
    int valid = (__fsub_rn(x2, x1) >= 1e-3f) && (__fsub_rn(y2, y1) >= 1e-3f);
    g_box[n * PITCH + j] = make_float4(x1, y1, x2, y2);
    g_lvlvalid[n * PITCH + j] = (unsigned char)((lvl << 1) | valid);
}

// ------------- K3b: stable per-(image,level) list build (NMS order) -------------
__global__ __launch_bounds__(512) void k3b_lists()
{
    __shared__ int sscan[512];
    __shared__ int stot;
    const int lvl = blockIdx.x, n = blockIdx.y, tid = threadIdx.x;
    int base = 0;
    for (int c0 = 0; c0 < KTOT; c0 += 512) {
        int j = c0 + tid;
        int flag = 0; unsigned char lv = 0;
        if (j < KTOT) { lv = g_lvlvalid[n * PITCH + j]; flag = ((lv >> 1) == lvl); }
        sscan[tid] = flag; __syncthreads();
        for (int off = 1; off < 512; off <<= 1) {
            int v = (tid >= off) ? sscan[tid - off] : 0;
            __syncthreads(); sscan[tid] += v; __syncthreads();
        }
        int incl = sscan[tid];
        if (tid == 511) stot = incl;
        if (flag) {
            int r = base + incl - 1;
            g_list[(n * 5 + lvl) * 1024 + r] = j;
            float4 b = g_box[n * PITCH + j];
            float of = __fmul_rn((float)lvl, 801.0f);
            g_lbox[(n * 5 + lvl) * 1024 + r] =
                make_float4(__fadd_rn(b.x, of), __fadd_rn(b.y, of),
                            __fadd_rn(b.z, of), __fadd_rn(b.w, of));
            g_lvalid[(n * 5 + lvl) * 1024 + r] = lv & 1;
        }
        __syncthreads();
        base += stot;
    }
}

// ------------- K4a: IoU>0.7 bit matrix (upper triangle), row-sliced -------------
__global__ __launch_bounds__(256) void k4a_iou()
{
    __shared__ float4 sb[1024];
    __shared__ float  sa[1024];
    const int lvl = blockIdx.x, n = blockIdx.y, sl = blockIdx.z, tid = threadIdx.x;
    const int M = c_KL[lvl];
    const float4* lb = &g_lbox[(n * 5 + lvl) * 1024];
    for (int t = tid; t < M; t += 256) {
        float4 b = lb[t]; sb[t] = b;
        sa[t] = __fmul_rn(__fsub_rn(b.z, b.x), __fsub_rn(b.w, b.y));
    }
    __syncthreads();
    const int W = (M + 63) >> 6;
    const int rows = (M + 7) / 8;
    const int r0 = sl * rows, r1 = min(r0 + rows, M);
    for (int t = tid;; t += 256) {
        int i = r0 + t / W;
        if (i >= r1) break;
        int w = t % W;
        int jstart = w << 6;
        int jend = min(jstart + 64, M);
        int js = max(jstart, i + 1);
        ull bits = 0;
        if (js < jend) {
            float4 bi = sb[i]; float ai = sa[i];
            for (int j = js; j < jend; j++) {
                float4 bj = sb[j];
                float ltx = fmaxf(bi.x, bj.x), lty = fmaxf(bi.y, bj.y);
                float rbx = fminf(bi.z, bj.z), rby = fminf(bi.w, bj.w);
                float wx = fmaxf(__fsub_rn(rbx, ltx), 0.f);
                float wy = fmaxf(__fsub_rn(rby, lty), 0.f);
                float inter = __fmul_rn(wx, wy);
                float uni = __fsub_rn(__fadd_rn(ai, sa[j]), inter);
                if (inter > __fmul_rn(0.7f, uni)) bits |= 1ull << (j - jstart);
            }
        }
        g_bits[(((size_t)(n * 5 + lvl) * 1024) + i) * 16 + w] = bits;
    }
}

// ------------- K4b: greedy NMS scan (one warp, bits in smem) -------------
__global__ __launch_bounds__(512) void k4b_scan()
{
    extern __shared__ ull sbits[];                // 1024*16
    __shared__ unsigned char sval[1024];
    const int lvl = blockIdx.x, n = blockIdx.y, tid = threadIdx.x;
    const int M = c_KL[lvl];
    const int W = (M + 63) >> 6;
    const ull* gb = &g_bits[(size_t)(n * 5 + lvl) * 1024 * 16];
    for (int t = tid; t < M * 16; t += 512) sbits[t] = gb[t];
    for (int t = tid; t < M; t += 512) sval[t] = g_lvalid[(n * 5 + lvl) * 1024 + t];
    __syncthreads();
    if (tid < 32) {
        ull sup = 0;
        const int lane = tid;
        for (int i = 0; i < M; i++) {
            int wi = i >> 6, bi = i & 63;
            ull supw = __shfl_sync(0xFFFFFFFFu, sup, wi);
            int kept = (((supw >> bi) & 1ull) == 0) && sval[i];
            if (kept && lane < W) sup |= sbits[i * 16 + lane];
            if (lane == 0) {
                int j = g_list[(n * 5 + lvl) * 1024 + i];
                g_keepj[n * PITCH + j] = (unsigned char)kept;
            }
        }
    }
}

// ------------- K5: stable keep-compaction -> output [fb | fs] -------------
__global__ __launch_bounds__(512) void k5_out(float* __restrict__ out)
{
    __shared__ int sscan[512];
    __shared__ int stot;
    const int n = blockIdx.x, tid = threadIdx.x;
    for (int t = tid; t < 4000; t += 512) out[n * 4000 + t] = 0.f;
    for (int t = tid; t < 1000; t += 512) out[16000 + n * 1000 + t] = 0.f;
    int base = 0;
    for (int c0 = 0; c0 < KTOT; c0 += 512) {
        int j = c0 + tid;
        int flag = (j < KTOT) ? (int)g_keepj[n * PITCH + j] : 0;
        sscan[tid] = flag; __syncthreads();
        for (int off = 1; off < 512; off <<= 1) {
            int v = (tid >= off) ? sscan[tid - off] : 0;
            __syncthreads(); sscan[tid] += v; __syncthreads();
        }
        int incl = sscan[tid];
        if (tid == 511) stot = incl;
        if (flag) {
            int r = base + incl - 1;
            if (r < 1000) {
                float4 b = g_box[n * PITCH + j];
                float* o = out + (size_t)(n * 1000 + r) * 4;
                o[0] = b.x; o[1] = b.y; o[2] = b.z; o[3] = b.w;
                out[16000 + n * 1000 + r] = g_score_srt[n * PITCH + j];
            }
        }
        __syncthreads();
        base += stot;
    }
}

extern "C" void kernel_launch(void* const* d_in, const int* in_sizes, int n_in,
                              void* d_out, int out_size) {
    const float *obj[5], *del[5], *anch;
    if (in_sizes[1] == 1920000) {   // interleaved: obj0,delta0,obj1,delta1,...
        for (int i = 0; i < 5; i++) { obj[i] = (const float*)d_in[2*i]; del[i] = (const float*)d_in[2*i+1]; }
    } else {                        // grouped: obj0..obj4, delta0..delta4
        for (int i = 0; i < 5; i++) { obj[i] = (const float*)d_in[i]; del[i] = (const float*)d_in[5+i]; }
    }
    anch = (const float*)d_in[10];

    cudaFuncSetAttribute(k2_sort, cudaFuncAttributeMaxDynamicSharedMemorySize, 65536);
    cudaFuncSetAttribute(k4b_scan, cudaFuncAttributeMaxDynamicSharedMemorySize, 131072);

    k1_topk  <<<dim3(5, 4), 512>>>(obj[0], obj[1], obj[2], obj[3], obj[4]);
    k2_sort  <<<4, 1024, 65536>>>();
    k3_decode<<<dim3(18, 4), 256>>>(del[0], del[1], del[2], del[3], del[4], anch);
    k3b_lists<<<dim3(5, 4), 512>>>();
    k4a_iou  <<<dim3(5, 4, 8), 256>>>();
    k4b_scan <<<dim3(5, 4), 512, 131072>>>();
    k5_out   <<<4, 512>>>((float*)d_out);
    (void)n_in; (void)out_size;
}